// round 2
// baseline (speedup 1.0000x reference)
#include <cuda_runtime.h>

// Problem constants (fixed shapes for this dataset)
#define BB   32
#define CC_  512
#define HH   56
#define WW   56
#define HW   (HH*WW)        // 3136
#define NCL  27
#define CHUNK 128           // channels per smem tile
#define NPIX (BB*HW)        // 100352
#define NPAIR (NPIX/2)      // 50176 (HW is even; pairs never cross images)

// Normalized clusters, duplicated into both halves of an f32x2 lane:
// g_cl2[n*C + c] = pack(v, v) where v = clusters[n][c] / ||clusters[n]||
__device__ unsigned long long g_cl2[NCL * CC_];

__device__ __forceinline__ unsigned long long fma2(unsigned long long a,
                                                   unsigned long long b,
                                                   unsigned long long c) {
    unsigned long long d;
    asm("fma.rn.f32x2 %0, %1, %2, %3;" : "=l"(d) : "l"(a), "l"(b), "l"(c));
    return d;
}

// One block (32 threads) per cluster row: L2-normalize + duplicate-pack.
__global__ void norm_clusters_kernel(const float* __restrict__ cl) {
    int n = blockIdx.x;
    int lane = threadIdx.x;
    float s = 0.f;
    #pragma unroll
    for (int c = lane; c < CC_; c += 32) {
        float v = cl[n * CC_ + c];
        s += v * v;
    }
    #pragma unroll
    for (int o = 16; o > 0; o >>= 1) s += __shfl_xor_sync(0xffffffffu, s, o);
    float inv = 1.0f / fmaxf(sqrtf(s), 1e-12f);
    #pragma unroll
    for (int c = lane; c < CC_; c += 32) {
        float v = cl[n * CC_ + c] * inv;
        float2 d = make_float2(v, v);
        g_cl2[n * CC_ + c] = *reinterpret_cast<unsigned long long*>(&d);
    }
}

__global__ void zero_out_kernel(float* out) { out[0] = 0.0f; }

__global__ void finalize_kernel(float* out) {
    out[0] = -out[0] / (float)NPIX;
}

// Main kernel: 2 adjacent pixels per thread, packed f32x2 math throughout.
__global__ __launch_bounds__(256, 2)
void cluster_main_kernel(const float* __restrict__ x, float* __restrict__ out) {
    __shared__ unsigned long long scl[NCL * CHUNK];

    int i = blockIdx.x * 256 + threadIdx.x;     // pair index in [0, NPAIR)
    int g = 2 * i;                              // first pixel (global)
    int b = g / HW;
    int p = g - b * HW;                         // pixel within image, even
    const float* xp = x + (size_t)b * CC_ * HW + p;

    unsigned long long acc[NCL];
    #pragma unroll
    for (int n = 0; n < NCL; n++) acc[n] = 0ull;
    unsigned long long nrm = 0ull;

    for (int c0 = 0; c0 < CC_; c0 += CHUNK) {
        __syncthreads();
        for (int t = threadIdx.x; t < NCL * CHUNK; t += 256) {
            int n = t / CHUNK;
            int c = t - n * CHUNK;
            scl[t] = g_cl2[n * CC_ + c0 + c];
        }
        __syncthreads();
        #pragma unroll 2
        for (int c = 0; c < CHUNK; c++) {
            unsigned long long xv =
                *reinterpret_cast<const unsigned long long*>(xp + (size_t)(c0 + c) * HW);
            nrm = fma2(xv, xv, nrm);
            #pragma unroll
            for (int n = 0; n < NCL; n++)
                acc[n] = fma2(xv, scl[n * CHUNK + c], acc[n]);
        }
    }

    // ---- epilogue: per-pixel normalize, softmax(2*inner), probs, loss ----
    float2 nf = *reinterpret_cast<float2*>(&nrm);
    float inv0 = 1.0f / fmaxf(sqrtf(nf.x), 1e-12f);
    float inv1 = 1.0f / fmaxf(sqrtf(nf.y), 1e-12f);

    float z0[NCL], z1[NCL];
    float m0 = -1e30f, m1 = -1e30f;
    #pragma unroll
    for (int n = 0; n < NCL; n++) {
        float2 d = *reinterpret_cast<float2*>(&acc[n]);
        z0[n] = 2.0f * d.x * inv0;              // alpha * inner, pixel 0
        z1[n] = 2.0f * d.y * inv1;              // alpha * inner, pixel 1
        m0 = fmaxf(m0, z0[n]);
        m1 = fmaxf(m1, z1[n]);
    }
    float s0 = 0.f, s1 = 0.f, l0 = 0.f, l1 = 0.f;
    #pragma unroll
    for (int n = 0; n < NCL; n++) {
        float e0 = __expf(z0[n] - m0);
        float e1 = __expf(z1[n] - m1);
        s0 += e0; s1 += e1;
        l0 += e0 * z0[n];                       // sum e * (alpha*inner)
        l1 += e1 * z1[n];
        z0[n] = e0; z1[n] = e1;
    }
    float rs0 = 1.0f / s0, rs1 = 1.0f / s1;

    // probs start at out+1 (loss occupies element 0) -> only 4B-aligned.
    // Must use scalar 32-bit stores; a float2 store here is a misaligned trap.
    float* po = out + 1;
    size_t base = (size_t)b * NCL * HW + p;
    #pragma unroll
    for (int n = 0; n < NCL; n++) {
        float* q = po + base + (size_t)n * HW;
        q[0] = z0[n] * rs0;
        q[1] = z1[n] * rs1;
    }

    // per-pixel loss contribution: sum_n prob * inner = (sum e*z) / (2*sum e)
    float l = l0 * rs0 * 0.5f + l1 * rs1 * 0.5f;
    #pragma unroll
    for (int o = 16; o > 0; o >>= 1) l += __shfl_xor_sync(0xffffffffu, l, o);
    if ((threadIdx.x & 31) == 0) atomicAdd(out, l);
}

extern "C" void kernel_launch(void* const* d_in, const int* in_sizes, int n_in,
                              void* d_out, int out_size) {
    const float* x  = (const float*)d_in[0];   // [32, 512, 56, 56]
    const float* cl = (const float*)d_in[1];   // [27, 512]
    float* out = (float*)d_out;                // [0]=loss, [1..]=probs [32,27,56,56]

    norm_clusters_kernel<<<NCL, 32>>>(cl);
    zero_out_kernel<<<1, 1>>>(out);
    cluster_main_kernel<<<NPAIR / 256, 256>>>(x, out);
    finalize_kernel<<<1, 1>>>(out);
}

// round 3
// speedup vs baseline: 1.3040x; 1.3040x over previous
#include <cuda_runtime.h>

// Problem constants (fixed shapes for this dataset)
#define BB   32
#define CC_  512
#define HH   56
#define WW   56
#define HW   (HH*WW)        // 3136
#define NCL  27
#define CHUNK 128           // channels per smem tile
#define NPIX (BB*HW)        // 100352
#define NPAIR (NPIX/2)      // 50176 (HW even; pairs never cross images)

// Normalized clusters, duplicated into both halves of an f32x2 lane:
// g_cl2[n*C + c] = pack(v, v) where v = clusters[n][c] / ||clusters[n]||
__device__ unsigned long long g_cl2[NCL * CC_];

__device__ __forceinline__ unsigned long long fma2(unsigned long long a,
                                                   unsigned long long b,
                                                   unsigned long long c) {
    unsigned long long d;
    asm("fma.rn.f32x2 %0, %1, %2, %3;" : "=l"(d) : "l"(a), "l"(b), "l"(c));
    return d;
}

// One block (32 threads) per cluster row: L2-normalize + duplicate-pack.
// Block 0 lane 0 also zeroes the loss accumulator (no separate kernel).
__global__ void prep_kernel(const float* __restrict__ cl, float* __restrict__ out) {
    int n = blockIdx.x;
    int lane = threadIdx.x;
    if (n == 0 && lane == 0) out[0] = 0.0f;
    float s = 0.f;
    #pragma unroll
    for (int c = lane; c < CC_; c += 32) {
        float v = cl[n * CC_ + c];
        s += v * v;
    }
    #pragma unroll
    for (int o = 16; o > 0; o >>= 1) s += __shfl_xor_sync(0xffffffffu, s, o);
    float inv = 1.0f / fmaxf(sqrtf(s), 1e-12f);
    #pragma unroll
    for (int c = lane; c < CC_; c += 32) {
        float v = cl[n * CC_ + c] * inv;
        float2 d = make_float2(v, v);
        g_cl2[n * CC_ + c] = *reinterpret_cast<unsigned long long*>(&d);
    }
}

// Main kernel: 2 adjacent pixels per thread (one f32x2 lane pair).
// LDS.128 fetches 2 channels of a cluster per instruction (halves LDS count);
// 8-wide x prefetch gives MLP=8 on the global loads.
__global__ __launch_bounds__(256, 2)
void cluster_main_kernel(const float* __restrict__ x, float* __restrict__ out) {
    __shared__ __align__(16) unsigned long long scl[NCL * CHUNK];

    int i = blockIdx.x * 256 + threadIdx.x;     // pair index in [0, NPAIR)
    int g = 2 * i;                              // first pixel (global)
    int b = g / HW;
    int p = g - b * HW;                         // pixel within image, even
    const float* xp = x + (size_t)b * CC_ * HW + p;

    unsigned long long acc[NCL];
    #pragma unroll
    for (int n = 0; n < NCL; n++) acc[n] = 0ull;
    unsigned long long nrm = 0ull;

    for (int c0 = 0; c0 < CC_; c0 += CHUNK) {
        __syncthreads();
        {   // fill smem tile with 16B vector copies
            const ulonglong2* src =
                reinterpret_cast<const ulonglong2*>(g_cl2);
            ulonglong2* dst = reinterpret_cast<ulonglong2*>(scl);
            for (int t = threadIdx.x; t < NCL * CHUNK / 2; t += 256) {
                int n = t / (CHUNK / 2);
                int c = t - n * (CHUNK / 2);
                dst[t] = src[n * (CC_ / 2) + c0 / 2 + c];
            }
        }
        __syncthreads();

        #pragma unroll 1
        for (int cc = 0; cc < CHUNK; cc += 8) {
            // front-batched x loads: MLP = 8
            unsigned long long xv[8];
            #pragma unroll
            for (int j = 0; j < 8; j++)
                xv[j] = *reinterpret_cast<const unsigned long long*>(
                    xp + (size_t)(c0 + cc + j) * HW);
            #pragma unroll
            for (int j = 0; j < 8; j += 2) {
                nrm = fma2(xv[j],     xv[j],     nrm);
                nrm = fma2(xv[j + 1], xv[j + 1], nrm);
                #pragma unroll
                for (int n = 0; n < NCL; n++) {
                    ulonglong2 w = *reinterpret_cast<const ulonglong2*>(
                        &scl[n * CHUNK + cc + j]);       // broadcast LDS.128
                    acc[n] = fma2(xv[j],     w.x, acc[n]);
                    acc[n] = fma2(xv[j + 1], w.y, acc[n]);
                }
            }
        }
    }

    // ---- epilogue: per-pixel normalize, softmax(2*inner), probs, loss ----
    float2 nf = *reinterpret_cast<float2*>(&nrm);
    float inv0 = 1.0f / fmaxf(sqrtf(nf.x), 1e-12f);
    float inv1 = 1.0f / fmaxf(sqrtf(nf.y), 1e-12f);

    float z0[NCL], z1[NCL];
    float m0 = -1e30f, m1 = -1e30f;
    #pragma unroll
    for (int n = 0; n < NCL; n++) {
        float2 d = *reinterpret_cast<float2*>(&acc[n]);
        z0[n] = 2.0f * d.x * inv0;              // alpha * inner, pixel 0
        z1[n] = 2.0f * d.y * inv1;              // alpha * inner, pixel 1
        m0 = fmaxf(m0, z0[n]);
        m1 = fmaxf(m1, z1[n]);
    }
    float s0 = 0.f, s1 = 0.f, l0 = 0.f, l1 = 0.f;
    #pragma unroll
    for (int n = 0; n < NCL; n++) {
        float e0 = __expf(z0[n] - m0);
        float e1 = __expf(z1[n] - m1);
        s0 += e0; s1 += e1;
        l0 += e0 * z0[n];                       // sum e * (alpha*inner)
        l1 += e1 * z1[n];
        z0[n] = e0; z1[n] = e1;
    }
    float rs0 = 1.0f / s0, rs1 = 1.0f / s1;

    // probs start at out+1 (loss occupies element 0) -> only 4B-aligned:
    // scalar 32-bit stores (a float2 store here is a misaligned-address trap).
    float* po = out + 1;
    size_t base = (size_t)b * NCL * HW + p;
    #pragma unroll
    for (int n = 0; n < NCL; n++) {
        float* q = po + base + (size_t)n * HW;
        q[0] = z0[n] * rs0;
        q[1] = z1[n] * rs1;
    }

    // loss: sum_n prob*inner = (sum e*z)/(2*sum e); fold in -1/NPIX here
    // so no finalize kernel is needed.
    float l = (l0 * rs0 + l1 * rs1) * (-0.5f / (float)NPIX);
    #pragma unroll
    for (int o = 16; o > 0; o >>= 1) l += __shfl_xor_sync(0xffffffffu, l, o);
    if ((threadIdx.x & 31) == 0) atomicAdd(out, l);
}

extern "C" void kernel_launch(void* const* d_in, const int* in_sizes, int n_in,
                              void* d_out, int out_size) {
    const float* x  = (const float*)d_in[0];   // [32, 512, 56, 56]
    const float* cl = (const float*)d_in[1];   // [27, 512]
    float* out = (float*)d_out;                // [0]=loss, [1..]=probs [32,27,56,56]

    prep_kernel<<<NCL, 32>>>(cl, out);
    cluster_main_kernel<<<NPAIR / 256, 256>>>(x, out);
}